// round 1
// baseline (speedup 1.0000x reference)
#include <cuda_runtime.h>

#define NPIX 16384   // 128*128 ROI pixels
#define NS   64      // sensors (LV_END - LV_START)
#define NT   2030    // time samples
#define NB   64      // batch

// Per-batch max scratch (nonnegative floats -> int-ordered atomicMax works)
__device__ float g_bmax[NB];

__global__ void init_kernel() {
    if (threadIdx.x < NB) g_bmax[threadIdx.x] = 0.0f;
}

__global__ __launch_bounds__(256) void das_kernel(
    const float* __restrict__ sino,   // [NB, NS, NT]
    const float* __restrict__ wts,    // [NPIX, NS]
    const int*   __restrict__ tidx,   // [NPIX, NS]
    float*       __restrict__ out)    // [NB*NPIX das][NB*NS*NPIX pixel_interp]
{
    const int b    = blockIdx.y;
    const int pix0 = (blockIdx.x * blockDim.x + threadIdx.x) * 4;

    const float* __restrict__ sb = sino + (size_t)b * NS * NT;
    float* __restrict__ pi = out + (size_t)NB * NPIX
                                 + (size_t)b * NS * NPIX + pix0;

    const int base = pix0 * NS;   // geometry row base for pixel pix0

    float acc0 = 0.f, acc1 = 0.f, acc2 = 0.f, acc3 = 0.f;

    #pragma unroll 4
    for (int s = 0; s < NS; ++s) {
        const float* __restrict__ srow = sb + s * NT;
        float4 v;

        {
            int   t = __ldg(tidx + base + 0 * NS + s);
            float w = __ldg(wts  + base + 0 * NS + s);
            w = (t >= 0 && t < NT) ? w : 0.0f;
            int tc = min(max(t, 0), NT - 1);
            v.x = __ldg(srow + tc) * w;  acc0 += v.x;
        }
        {
            int   t = __ldg(tidx + base + 1 * NS + s);
            float w = __ldg(wts  + base + 1 * NS + s);
            w = (t >= 0 && t < NT) ? w : 0.0f;
            int tc = min(max(t, 0), NT - 1);
            v.y = __ldg(srow + tc) * w;  acc1 += v.y;
        }
        {
            int   t = __ldg(tidx + base + 2 * NS + s);
            float w = __ldg(wts  + base + 2 * NS + s);
            w = (t >= 0 && t < NT) ? w : 0.0f;
            int tc = min(max(t, 0), NT - 1);
            v.z = __ldg(srow + tc) * w;  acc2 += v.z;
        }
        {
            int   t = __ldg(tidx + base + 3 * NS + s);
            float w = __ldg(wts  + base + 3 * NS + s);
            w = (t >= 0 && t < NT) ? w : 0.0f;
            int tc = min(max(t, 0), NT - 1);
            v.w = __ldg(srow + tc) * w;  acc3 += v.w;
        }

        // coalesced 128B/warp store of the dominant output stream
        *reinterpret_cast<float4*>(pi + (size_t)s * NPIX) = v;
    }

    // das = relu(sum_s weighted), stored raw; normalized by kernel 3
    float4 d;
    d.x = fmaxf(acc0, 0.f);
    d.y = fmaxf(acc1, 0.f);
    d.z = fmaxf(acc2, 0.f);
    d.w = fmaxf(acc3, 0.f);
    *reinterpret_cast<float4*>(out + (size_t)b * NPIX + pix0) = d;

    // block max -> per-batch atomicMax
    float m = fmaxf(fmaxf(d.x, d.y), fmaxf(d.z, d.w));
    #pragma unroll
    for (int off = 16; off > 0; off >>= 1)
        m = fmaxf(m, __shfl_xor_sync(0xffffffffu, m, off));

    __shared__ float smax[8];
    if ((threadIdx.x & 31) == 0) smax[threadIdx.x >> 5] = m;
    __syncthreads();
    if (threadIdx.x == 0) {
        float mm = smax[0];
        #pragma unroll
        for (int i = 1; i < 8; ++i) mm = fmaxf(mm, smax[i]);
        atomicMax(reinterpret_cast<int*>(&g_bmax[b]), __float_as_int(mm));
    }
}

__global__ __launch_bounds__(256) void norm_kernel(float* __restrict__ out)
{
    // normalize the das region: NB*NPIX floats, processed as float4
    int i = blockIdx.x * blockDim.x + threadIdx.x;    // 0 .. NB*NPIX/4-1
    float4* p = reinterpret_cast<float4*>(out);
    float4 v = p[i];
    int b = (i * 4) >> 14;                             // /NPIX
    float m = g_bmax[b];
    float r = (m > 1e-8f) ? (1.0f / m) : 1.0f;
    v.x *= r; v.y *= r; v.z *= r; v.w *= r;
    p[i] = v;
}

extern "C" void kernel_launch(void* const* d_in, const int* in_sizes, int n_in,
                              void* d_out, int out_size)
{
    const float* sino = (const float*)d_in[0];   // [64,1,64,2030]
    const float* wts  = (const float*)d_in[1];   // [128,128,64]
    const int*   tidx = (const int*)d_in[2];     // [128,128,64]
    // d_in[3] = valid_mask: ignored; validity is recomputed from tidx
    float* out = (float*)d_out;

    init_kernel<<<1, 64>>>();

    dim3 grid(NPIX / (256 * 4), NB);  // (16, 64)
    das_kernel<<<grid, 256>>>(sino, wts, tidx, out);

    norm_kernel<<<(NB * NPIX / 4) / 256, 256>>>(out);
}

// round 2
// speedup vs baseline: 4.3560x; 4.3560x over previous
#include <cuda_runtime.h>

#define NPIX 16384   // 128*128 ROI pixels
#define NS   64      // sensors
#define NT   2030    // time samples
#define NB   64      // batch
#define BQ   8       // batches per block
#define SNT  (NS*NT) // sinogram batch stride = 129920

// Transposed, pre-masked geometry: [s][pix]
__device__ int   g_tT[NS * NPIX];
__device__ float g_wT[NS * NPIX];
__device__ float g_bmax[NB];

__global__ void init_kernel() {
    if (threadIdx.x < NB) g_bmax[threadIdx.x] = 0.0f;
}

// Tiled transpose [pix][s] -> [s][pix], baking clamp + validity into t/w.
__global__ __launch_bounds__(1024) void prep_kernel(
    const float* __restrict__ wts, const int* __restrict__ tidx)
{
    __shared__ int   ts[32][33];
    __shared__ float ws[32][33];
    const int p0 = blockIdx.x * 32;
    const int s0 = blockIdx.y * 32;
    const int tx = threadIdx.x, ty = threadIdx.y;

    // coalesced read: row = pixel, col = s (s contiguous)
    int   t = tidx[(p0 + ty) * NS + s0 + tx];
    float w = wts [(p0 + ty) * NS + s0 + tx];
    w = (t >= 0 && t < NT) ? w : 0.0f;
    t = min(max(t, 0), NT - 1);
    ts[ty][tx] = t;
    ws[ty][tx] = w;
    __syncthreads();

    // coalesced write: row = s, col = pixel
    g_tT[(s0 + ty) * NPIX + p0 + tx] = ts[tx][ty];
    g_wT[(s0 + ty) * NPIX + p0 + tx] = ws[tx][ty];
}

__global__ __launch_bounds__(128) void das_kernel(
    const float* __restrict__ sino,   // [NB, NS, NT]
    float*       __restrict__ out)    // [NB*NPIX das | NB*NS*NPIX pixel_interp]
{
    const int pix = blockIdx.x * 128 + threadIdx.x;
    const int b0  = blockIdx.y * BQ;

    const float* __restrict__ sb = sino + b0 * SNT;
    float* __restrict__ pi = out + NB * NPIX + (b0 * NS) * NPIX + pix;

    float acc[BQ];
    #pragma unroll
    for (int q = 0; q < BQ; ++q) acc[q] = 0.0f;

    int gi = pix;                 // g_tT/g_wT index, += NPIX per s
    int po = 0;                   // pixel_interp offset within batch-group, += NPIX per s

    for (int s = 0; s < NS; ++s) {
        const int   t = g_tT[gi];
        const float w = g_wT[gi];
        const float* __restrict__ src = sb + s * NT + t;

        #pragma unroll
        for (int q = 0; q < BQ; ++q) {
            float v = __ldg(src + q * SNT) * w;
            acc[q] += v;
            pi[po + q * (NS * NPIX)] = v;
        }
        gi += NPIX;
        po += NPIX;
    }

    // das = relu(sum), store raw (normalized by norm_kernel)
    float bm[BQ];
    #pragma unroll
    for (int q = 0; q < BQ; ++q) {
        float d = fmaxf(acc[q], 0.0f);
        out[(b0 + q) * NPIX + pix] = d;
        bm[q] = d;
    }

    // per-batch block max -> atomicMax (nonneg floats: int ordering works)
    __shared__ float smax[4][BQ];   // 4 warps
    const int lane = threadIdx.x & 31, wrp = threadIdx.x >> 5;
    #pragma unroll
    for (int q = 0; q < BQ; ++q) {
        float m = bm[q];
        #pragma unroll
        for (int off = 16; off > 0; off >>= 1)
            m = fmaxf(m, __shfl_xor_sync(0xffffffffu, m, off));
        if (lane == 0) smax[wrp][q] = m;
    }
    __syncthreads();
    if (threadIdx.x < BQ) {
        float m = smax[0][threadIdx.x];
        #pragma unroll
        for (int wq = 1; wq < 4; ++wq) m = fmaxf(m, smax[wq][threadIdx.x]);
        atomicMax(reinterpret_cast<int*>(&g_bmax[b0 + threadIdx.x]),
                  __float_as_int(m));
    }
}

__global__ __launch_bounds__(256) void norm_kernel(float* __restrict__ out)
{
    int i = blockIdx.x * blockDim.x + threadIdx.x;    // 0 .. NB*NPIX/4-1
    float4* p = reinterpret_cast<float4*>(out);
    float4 v = p[i];
    int b = (i * 4) >> 14;                            // / NPIX
    float m = g_bmax[b];
    float r = (m > 1e-8f) ? (1.0f / m) : 1.0f;
    v.x *= r; v.y *= r; v.z *= r; v.w *= r;
    p[i] = v;
}

extern "C" void kernel_launch(void* const* d_in, const int* in_sizes, int n_in,
                              void* d_out, int out_size)
{
    const float* sino = (const float*)d_in[0];   // [64,1,64,2030]
    const float* wts  = (const float*)d_in[1];   // [128,128,64]
    const int*   tidx = (const int*)d_in[2];     // [128,128,64]
    float* out = (float*)d_out;

    init_kernel<<<1, 64>>>();

    dim3 pgrid(NPIX / 32, NS / 32);               // (512, 2)
    prep_kernel<<<pgrid, dim3(32, 32)>>>(wts, tidx);

    dim3 grid(NPIX / 128, NB / BQ);               // (128, 8) = 1024 blocks
    das_kernel<<<grid, 128>>>(sino, out);

    norm_kernel<<<(NB * NPIX / 4) / 256, 256>>>(out);
}